// round 14
// baseline (speedup 1.0000x reference)
#include <cuda_runtime.h>

#define Bc   8
#define Sc   8192
#define Vc   64
#define Dc   256
#define DVc  32
#define DAGG 224
#define CAP  Sc

// K1 layout
#define SCAN_N 128
#define ABC_N  32
#define ABC0   SCAN_N              // 128
#define PQK0   (ABC0 + ABC_N)      // 160
#define PF0    (PQK0 + Vc)         // 224
#define PF_N   20
#define K1_N   (PF0 + PF_N)        // 244
// K3 layout
#define UB0    Vc                  // 64
#define K3_N   (UB0 + 8)           // 72
// K4 layout
#define K4_N   (Bc * 16)           // 128 blocks, single wave

// ---- device globals (zero-init; all mutated state self-resets) ----
__device__ float  g_A[DAGG], g_Bv[DAGG], g_C[DAGG];
__device__ float  g_part[ABC_N][3][DAGG];
__device__ int    g_abc_ctr;
__device__ float  g_pa[3][Dc], g_pb[3][Dc], g_pc[3][Dc];   // 0=q,1=k,2=v
__device__ float  g_SV0[Dc];
__device__ float  g_Pq[Vc][Dc], g_Pk[Vc][Dc];              // ve @ W[0:32]
__device__ int    g_cnt[Bc * Vc];
__device__ float2 g_tok[Bc * Vc * CAP];
__device__ float  g_corr[Bc][Dc];
__device__ int    g_corrflag;
__device__ float  g_sumwv[Bc][8], g_sumwt[Bc][8];
__device__ float  g_Ua[8][Dc], g_Ub[8][Dc], g_U0[Dc];
__device__ float  g_p2s[Bc][16];
__device__ int    g_ctr4[Bc], g_ctr4g;
__device__ int    g_maskflags;      // sticky across replays (OR idempotent)
__device__ float  g_sink;           // prefetch DCE guard

// ============================ K1 (all branches independent) ============================
__global__ void __launch_bounds__(256) k1(
        const float* __restrict__ times, const int* __restrict__ fid,
        const float* __restrict__ values, const void* __restrict__ mask,
        const float* __restrict__ me_w, const float* __restrict__ me_b,
        const float* __restrict__ var_emb,
        const float* __restrict__ time_w, const float* __restrict__ time_b,
        const float* __restrict__ agg_w, const float* __restrict__ agg_b,
        const float* __restrict__ wq, const float* __restrict__ wk,
        const float* __restrict__ wv, const float* __restrict__ wo,
        const float* __restrict__ cw1) {
    const int blk = blockIdx.x, tid = threadIdx.x;

    if (blk < ABC0) {
        // ---- token scan: 512 tokens/block (2/thread), local layout detect ----
        int sb = blk;
        __shared__ int sfl;
        if (tid == 0) sfl = g_maskflags;
        __syncthreads();
        if (tid < 128) {   // covers this block's byte-layout window
            unsigned w = ((const unsigned*)mask)[sb * 128 + tid];
            if (w > 1u && w != 0x3f800000u) atomicOr(&sfl, 1);
        }
        __syncthreads();
        int fl = sfl;
        if (tid == 0 && fl) atomicOr(&g_maskflags, fl);

        int tp = sb * 256 + tid;      // token-pair index
        bool ok0, ok1;
        if (fl & 1) {
            unsigned short us = ((const unsigned short*)mask)[tp];
            ok0 = (us & 0xffu) != 0; ok1 = (us >> 8) != 0;
        } else {          // int32 / float32: identical nonzero bit test
            int2 m2 = ((const int2*)mask)[tp];
            ok0 = m2.x != 0; ok1 = m2.y != 0;
        }
        if (ok0 | ok1) {
            float2 vv = ((const float2*)values)[tp];
            float2 tt = ((const float2*)times)[tp];
            int2   ff = ((const int2*)fid)[tp];
            int b = tp >> 12;
            if (ok0) {
                int bvx = b * Vc + ff.x;
                int pos = atomicAdd(&g_cnt[bvx], 1);
                g_tok[bvx * CAP + pos] = make_float2(vv.x, tt.x);
            }
            if (ok1) {
                int bvx = b * Vc + ff.y;
                int pos = atomicAdd(&g_cnt[bvx], 1);
                g_tok[bvx * CAP + pos] = make_float2(vv.y, tt.y);
            }
        }

    } else if (blk < PQK0) {
        // ---- ABC: rank-2 collapse partials + last-block counter reduce ----
        int ab = blk - ABC0;
        int j = tid;
        __shared__ bool isLast;
        if (j < DAGG) {
            float a = 0.f, b = 0.f, c = 0.f;
            int i0 = ab * 16;
            #pragma unroll
            for (int ii = 0; ii < 16; ii++) {
                int i = i0 + ii;
                if (i < 256) {
                    float w = agg_w[i * DAGG + j];
                    a += me_w[i] * w;  c += me_b[i] * w;
                } else {
                    int k = i - 256;
                    float w = agg_w[(256 + k) * DAGG + j];
                    b += time_w[k] * w;  c += time_b[k] * w;
                }
            }
            g_part[ab][0][j] = a; g_part[ab][1][j] = b; g_part[ab][2][j] = c;
        }
        __threadfence();
        __syncthreads();
        if (tid == 0) isLast = (atomicAdd(&g_abc_ctr, 1) == ABC_N - 1);
        __syncthreads();
        if (isLast) {
            if (j < DAGG) {
                float a = 0.f, b = 0.f, c = 0.f;
                #pragma unroll
                for (int r = 0; r < ABC_N; r++) {
                    a += __ldcg(&g_part[r][0][j]);
                    b += __ldcg(&g_part[r][1][j]);
                    c += __ldcg(&g_part[r][2][j]);
                }
                g_A[j] = a; g_Bv[j] = b; g_C[j] = c + agg_b[j];
            }
            if (tid == 0) g_abc_ctr = 0;   // reset for next replay
        }

    } else if (blk < PF0) {
        // ---- PQK: Pq[v] = ve @ wq[0:32], Pk[v] = ve @ wk[0:32] ----
        int v = blk - PQK0;
        __shared__ float ve[DVc];
        if (tid < DVc) ve[tid] = var_emb[v * DVc + tid];
        __syncthreads();
        int j = tid;
        float sq = 0.f, sk = 0.f;
        #pragma unroll
        for (int i = 0; i < DVc; i++) {
            float e = ve[i];
            sq += e * wq[i * Dc + j];
            sk += e * wk[i * Dc + j];
        }
        g_Pq[v][j] = sq;
        g_Pk[v][j] = sk;

    } else {
        // ---- PF: warm L2 with the weights later kernels need ----
        int chunk = blk - PF0;                 // 0..19
        const float4* srcs[5] = { (const float4*)wq, (const float4*)wk,
                                  (const float4*)wv, (const float4*)wo,
                                  (const float4*)cw1 };
        const float4* s4 = srcs[chunk >> 2];
        int base = (chunk & 3) * 4096 + tid;   // 4096 float4 per chunk
        float acc = 0.f;
        #pragma unroll
        for (int i = 0; i < 16; i++) {
            float4 w = __ldcg(&s4[base + i * 256]);
            acc += w.x + w.y + w.z + w.w;
        }
        if (acc == 1.2345e-37f) g_sink = acc;  // DCE guard, never taken
    }
}

// ============================ K2: VEC (+SV0 in block 8) ============================
__global__ void __launch_bounds__(1024) k2(
        const float* __restrict__ var_emb,
        const float* __restrict__ wq, const float* __restrict__ bq,
        const float* __restrict__ wk, const float* __restrict__ bk,
        const float* __restrict__ wv, const float* __restrict__ bv) {
    const int u = blockIdx.x, tid = threadIdx.x;
    const int p = u / 3, r = u % 3;
    const int j = tid & 255, half = tid >> 8;   // 4-way i-split
    const float* W   = (p == 0) ? wq : (p == 1 ? wk : wv);
    const float* bbp = (p == 0) ? bq : (p == 1 ? bk : bv);
    const float* src = (r == 0) ? g_A : (r == 1 ? g_Bv : g_C);

    __shared__ float part[4][Dc];
    __shared__ float pcl[Dc];
    __shared__ float sve[DVc];
    __shared__ float sp[32][DVc];

    float s = 0.f;
    #pragma unroll 14
    for (int ii = 0; ii < 56; ii++) {
        int i = half * 56 + ii;
        s += src[i] * W[(DVc + i) * Dc + j];
    }
    part[half][j] = s;
    __syncthreads();

    float val = 0.f;
    if (half == 0) {
        val = part[0][j] + part[1][j] + part[2][j] + part[3][j];
        if (r == 2) val += bbp[j];
        if      (r == 0) g_pa[p][j] = val;
        else if (r == 1) g_pb[p][j] = val;
        else             g_pc[p][j] = val;
    }

    if (p == 2 && r == 2) {   // block-uniform: also compute SV0 here
        if (half == 0) pcl[j] = val;
        int lane = tid & 31, grp = tid >> 5;   // grp 0..31
        sp[grp][lane] = var_emb[(2 * grp) * DVc + lane]
                      + var_emb[(2 * grp + 1) * DVc + lane];
        __syncthreads();
        if (grp == 0) {
            float s2 = 0.f;
            #pragma unroll
            for (int g = 0; g < 32; g++) s2 += sp[g][lane];
            sve[lane] = s2;
        }
        __syncthreads();
        if (half == 0) {
            float s3 = 64.f * pcl[j];
            #pragma unroll
            for (int k = 0; k < DVc; k++) s3 += sve[k] * wv[k * Dc + j];
            g_SV0[j] = s3;
        }
    }
}

// ============================ K3: SOFT + U ============================
__global__ void __launch_bounds__(256) k3(
        const int* __restrict__ fid, const float* __restrict__ values,
        const float* __restrict__ times, const float* __restrict__ var_emb,
        const float* __restrict__ wv, const float* __restrict__ wo,
        const float* __restrict__ bo) {
    const int blk = blockIdx.x, tid = threadIdx.x;
    const int h = tid >> 5, lane = tid & 31;

    if (blk < UB0) {
        // ---- SOFT: per-v head coefficients + scalar segmented softmax ----
        int v = blk;
        __shared__ float sc[8][9];

        int j = tid;
        float qa = g_pa[0][j], qb = g_pb[0][j];
        float ka = g_pa[1][j], kb = g_pb[1][j];
        float p0 = g_pc[0][j] + g_Pq[v][j];
        float k0 = g_pc[1][j] + g_Pk[v][j];

        const float scale = 0.17677669529663687f;   // 1/sqrt(32)
        float x[9] = { p0 * k0, qa * k0, qb * k0,
                       p0 * ka, qa * ka, qb * ka,
                       p0 * kb, qa * kb, qb * kb };
        #pragma unroll
        for (int t = 0; t < 9; t++) {
            float s = x[t];
            #pragma unroll
            for (int o = 16; o > 0; o >>= 1) s += __shfl_xor_sync(0xffffffffu, s, o);
            if (lane == 0) sc[h][t] = s * scale;
        }
        __syncthreads();

        int b = h;                 // warp h handles batch b
        int bvx = b * Vc + v;
        int n = g_cnt[bvx];

        if (n == 0) {
            // reference unmasks s=0 -> ctx = v_proj[b,0,:]
            int t0g = b * Sc;
            int f0 = fid[t0g];
            float val0 = values[t0g], tt0 = times[t0g];
            const float* vef = &var_emb[f0 * DVc];
            const float* veo = &var_emb[v  * DVc];
            for (int j2 = lane; j2 < Dc; j2 += 32) {
                float d = 0.f;
                #pragma unroll
                for (int i = 0; i < DVc; i++) d += (vef[i] - veo[i]) * wv[i * Dc + j2];
                atomicAdd(&g_corr[b][j2], d);
            }
            if (lane == 0) g_corrflag = 1;
            if (lane < 8) {
                atomicAdd(&g_sumwv[b][lane], val0);
                atomicAdd(&g_sumwt[b][lane], tt0);
            }
            return;
        }

        const float2* tok = &g_tok[bvx * CAP];
        float s_v = 0.f, s_t = 0.f;
        for (int i = lane; i < n; i += 32) {
            float2 t = tok[i];
            s_v += t.x; s_t += t.y;
        }
        #pragma unroll
        for (int o = 16; o > 0; o >>= 1) {
            s_v += __shfl_xor_sync(0xffffffffu, s_v, o);
            s_t += __shfl_xor_sync(0xffffffffu, s_t, o);
        }
        float inv_n = 1.0f / (float)n;
        float mvv = s_v * inv_n, mtt = s_t * inv_n;

        float al[8], be[8], ga[8];
        #pragma unroll
        for (int t = 0; t < 8; t++) {
            al[t] = sc[t][0] + mvv * sc[t][1] + mtt * sc[t][2];
            be[t] = sc[t][3] + mvv * sc[t][4] + mtt * sc[t][5];
            ga[t] = sc[t][6] + mvv * sc[t][7] + mtt * sc[t][8];
        }
        float m[8], l[8], sv[8], st[8];
        #pragma unroll
        for (int t = 0; t < 8; t++) { m[t] = -1e30f; l[t] = 0.f; sv[t] = 0.f; st[t] = 0.f; }
        for (int i = lane; i < n; i += 32) {
            float2 t2 = tok[i];
            #pragma unroll
            for (int t = 0; t < 8; t++) {
                float s  = al[t] + be[t] * t2.x + ga[t] * t2.y;
                float nm = fmaxf(m[t], s);
                float c  = __expf(m[t] - nm);
                float e  = __expf(s - nm);
                l[t]  = l[t] * c + e;
                sv[t] = sv[t] * c + e * t2.x;
                st[t] = st[t] * c + e * t2.y;
                m[t] = nm;
            }
        }
        #pragma unroll
        for (int t = 0; t < 8; t++) {
            #pragma unroll
            for (int o = 16; o > 0; o >>= 1) {
                float m2  = __shfl_xor_sync(0xffffffffu, m[t], o);
                float l2  = __shfl_xor_sync(0xffffffffu, l[t], o);
                float sv2 = __shfl_xor_sync(0xffffffffu, sv[t], o);
                float st2 = __shfl_xor_sync(0xffffffffu, st[t], o);
                float nm = fmaxf(m[t], m2);
                float c1 = __expf(m[t] - nm), c2 = __expf(m2 - nm);
                l[t]  = l[t] * c1 + l2 * c2;
                sv[t] = sv[t] * c1 + sv2 * c2;
                st[t] = st[t] * c1 + st2 * c2;
                m[t] = nm;
            }
        }
        if (lane == 0) {
            #pragma unroll
            for (int t = 0; t < 8; t++) {
                atomicAdd(&g_sumwv[b][t], sv[t] / l[t]);
                atomicAdd(&g_sumwt[b][t], st[t] / l[t]);
            }
            g_cnt[bvx] = 0;    // reset for next replay
        }

    } else {
        // ---- U-vectors: U0, Ua[h], Ub[h] (32-col slice per block) ----
        int sl = blk - UB0;
        int col = sl * 32 + lane;
        float aa = 0.f, bb2 = 0.f, cc = 0.f;
        #pragma unroll
        for (int k = 0; k < 32; k++) {
            int d = h * 32 + k;
            float w_ = wo[d * Dc + col];
            aa  += g_pa[2][d] * w_;
            bb2 += g_pb[2][d] * w_;
            cc  += g_SV0[d]   * w_;
        }
        g_Ua[h][col] = aa * (1.f / 64.f);
        g_Ub[h][col] = bb2 * (1.f / 64.f);
        __shared__ float up[8][32];
        up[h][lane] = cc;
        __syncthreads();
        if (h == 0) {
            float s = 0.f;
            #pragma unroll
            for (int r = 0; r < 8; r++) s += up[r][lane];
            g_U0[col] = s * (1.f / 64.f) + bo[col];
        }
    }
}

// ============================ K4: FIN, 128 blocks (b x 16 col-slices) ============================
__global__ void __launch_bounds__(256) k4(
        const float* __restrict__ wo,
        const float* __restrict__ cw1, const float* __restrict__ cb1,
        const float* __restrict__ cw2, const float* __restrict__ cb2,
        float* __restrict__ out) {
    const int blk = blockIdx.x;
    const int b = blk >> 4, sl = blk & 15;
    const int tid = threadIdx.x;
    __shared__ float  ssf[Dc];
    __shared__ float4 part4[64][4];
    __shared__ float  swv[8], swt[8];
    __shared__ bool   isLastB;

    if (tid < 8)       swv[tid] = g_sumwv[b][tid];
    else if (tid < 16) swt[tid - 8] = g_sumwt[b][tid - 8];
    int cfl = g_corrflag;
    __syncthreads();

    // reconstruct sf(b): U0 + rank-16 head combo (+ cold corr path)
    {
        float sf = g_U0[tid];
        #pragma unroll
        for (int t = 0; t < 8; t++)
            sf += swv[t] * g_Ua[t][tid] + swt[t] * g_Ub[t][tid];
        if (cfl) {
            float cd = 0.f;
            for (int d = 0; d < Dc; d++) cd += g_corr[b][d] * wo[d * Dc + tid];
            sf += cd * (1.f / 64.f);
        }
        ssf[tid] = sf;
    }
    __syncthreads();

    // GEMV2 slice: 16 output cols (= 4 float4 cols), 64-way i-split
    int ip = tid >> 2, f4 = tid & 3;        // ip: 0..63, f4: 0..3
    int col4 = sl * 4 + f4;                 // global float4 column
    const float4* W4 = (const float4*)cw1;
    float4 acc = make_float4(0.f, 0.f, 0.f, 0.f);
    #pragma unroll
    for (int k = 0; k < 4; k++) {
        float  s = ssf[ip * 4 + k];
        float4 w = W4[(ip * 4 + k) * 64 + col4];
        acc.x += s * w.x; acc.y += s * w.y; acc.z += s * w.z; acc.w += s * w.w;
    }
    part4[ip][f4] = acc;
    __syncthreads();
    #pragma unroll
    for (int sred = 32; sred > 0; sred >>= 1) {
        if (ip < sred) {
            float4 o2 = part4[ip + sred][f4];
            part4[ip][f4].x += o2.x; part4[ip][f4].y += o2.y;
            part4[ip][f4].z += o2.z; part4[ip][f4].w += o2.w;
        }
        __syncthreads();
    }
    if (tid < 4) {
        float4 t  = part4[0][tid];
        float4 cb = ((const float4*)cb1)[sl * 4 + tid];
        float4 w2 = ((const float4*)cw2)[sl * 4 + tid];
        float c = fmaxf(t.x + cb.x, 0.f) * w2.x + fmaxf(t.y + cb.y, 0.f) * w2.y
                + fmaxf(t.z + cb.z, 0.f) * w2.z + fmaxf(t.w + cb.w, 0.f) * w2.w;
        c += __shfl_xor_sync(0x0000000fu, c, 1);
        c += __shfl_xor_sync(0x0000000fu, c, 2);
        if (tid == 0) g_p2s[b][sl] = c;
    }
    __threadfence();
    __syncthreads();
    if (tid == 0)
        isLastB = (atomicAdd(&g_ctr4[b], 1) == 15);
    __syncthreads();
    if (isLastB) {
        if (tid == 0) {
            float tot = 0.f;
            #pragma unroll
            for (int k = 0; k < 16; k++) tot += __ldcg(&g_p2s[b][k]);
            out[b] = tot + cb2[0];
            g_ctr4[b] = 0;                     // reset for next replay
        }
        // per-b resets (all 16 blocks of this b already read these)
        if (tid < 8)       g_sumwv[b][tid] = 0.f;
        else if (tid < 16) g_sumwt[b][tid - 8] = 0.f;
        if (cfl) g_corr[b][tid] = 0.f;
        __threadfence();
        __syncthreads();
        if (tid == 0 && atomicAdd(&g_ctr4g, 1) == Bc - 1) {
            g_corrflag = 0;                    // last of all 8 finalizers
            g_ctr4g = 0;
        }
    }
}

// ---------------- launch ----------------
extern "C" void kernel_launch(void* const* d_in, const int* in_sizes, int n_in,
                              void* d_out, int out_size) {
    const float* times   = (const float*)d_in[0];
    const int*   fid     = (const int*)  d_in[1];
    const float* values  = (const float*)d_in[2];
    const void*  mask    = (const void*) d_in[3];
    const float* me_w    = (const float*)d_in[4];
    const float* me_b    = (const float*)d_in[5];
    const float* var_emb = (const float*)d_in[6];
    const float* time_w  = (const float*)d_in[7];
    const float* time_b  = (const float*)d_in[8];
    const float* agg_w   = (const float*)d_in[9];
    const float* agg_b   = (const float*)d_in[10];
    const float* wq = (const float*)d_in[11]; const float* bq  = (const float*)d_in[12];
    const float* wk = (const float*)d_in[13]; const float* bk  = (const float*)d_in[14];
    const float* wv = (const float*)d_in[15]; const float* bv  = (const float*)d_in[16];
    const float* wo = (const float*)d_in[17]; const float* bo  = (const float*)d_in[18];
    const float* cw1 = (const float*)d_in[19]; const float* cb1 = (const float*)d_in[20];
    const float* cw2 = (const float*)d_in[21]; const float* cb2 = (const float*)d_in[22];
    float* out = (float*)d_out;

    k1<<<K1_N, 256>>>(times, fid, values, mask,
                      me_w, me_b, var_emb, time_w, time_b, agg_w, agg_b,
                      wq, wk, wv, wo, cw1);
    k2<<<9, 1024>>>(var_emb, wq, bq, wk, bk, wv, bv);
    k3<<<K3_N, 256>>>(fid, values, times, var_emb, wv, wo, bo);
    k4<<<K4_N, 256>>>(wo, cw1, cb1, cw2, cb2, out);
}

// round 15
// speedup vs baseline: 1.2963x; 1.2963x over previous
#include <cuda_runtime.h>
#include <math.h>

#define Bc   8
#define Sc   8192
#define Vc   64
#define Dc   256
#define DVc  32
#define DAGG 224     // D - DV
#define NTOK (Bc*Sc) // 65536
#define NBV  (Bc*Vc) // 512
#define CAP  Sc      // worst-case tokens per (b,v) segment
#define ABC_BLKS 32
#define PF_BLKS  32  // prefetch blocks appended to k_mid

// ---------------- scratch (device globals; no allocation) ----------------
__device__ float  g_A[DAGG], g_Bv[DAGG], g_C[DAGG];
__device__ float  g_part[ABC_BLKS][3][DAGG];
__device__ int    g_abc_ctr = 0;                           // self-resetting
__device__ float  g_pa[3][Dc], g_pb[3][Dc], g_pc[3][Dc];   // 0=q,1=k,2=v
__device__ float  g_Pvar[3][Vc][Dc];                       // var_emb @ W[0:32,:]
__device__ int    g_cnt[NBV];
__device__ float2 g_tok[NBV * CAP];                        // (val,tt) per segment
__device__ float  g_ctx[Bc][Dc];
__device__ float  g_sf[Bc][Dc];
__device__ float  g_p2[Bc][8];
__device__ int    g_ctr2[Bc];                              // zero-init, self-resetting
__device__ int    g_maskflags = 0;   // bit0: byte layout, bit1: float layout (OR idempotent)
__device__ float  g_sink;            // prefetch DCE guard

// ---------------- K1: parallel ABC collapse + mask detect + zero ----------------
__global__ void k_init(const float* __restrict__ me_w, const float* __restrict__ me_b,
                       const float* __restrict__ time_w, const float* __restrict__ time_b,
                       const float* __restrict__ agg_w, const float* __restrict__ agg_b,
                       const void* __restrict__ mask) {
    int blk = blockIdx.x;
    if (blk < ABC_BLKS) {
        int j = threadIdx.x;
        __shared__ bool isLast;
        if (j < DAGG) {
            float a = 0.f, b = 0.f, c = 0.f;
            int i0 = blk * 16;
            #pragma unroll
            for (int ii = 0; ii < 16; ii++) {
                int i = i0 + ii;
                if (i < 256) {
                    float w = agg_w[i * DAGG + j];
                    a += me_w[i] * w;  c += me_b[i] * w;
                } else {
                    int k = i - 256;
                    float w = agg_w[(256 + k) * DAGG + j];
                    b += time_w[k] * w;  c += time_b[k] * w;
                }
            }
            g_part[blk][0][j] = a;
            g_part[blk][1][j] = b;
            g_part[blk][2][j] = c;
        }
        __threadfence();
        __syncthreads();
        if (threadIdx.x == 0)
            isLast = (atomicAdd(&g_abc_ctr, 1) == ABC_BLKS - 1);
        __syncthreads();
        if (isLast) {
            if (j < DAGG) {
                float a = 0.f, b = 0.f, c = 0.f;
                #pragma unroll
                for (int r = 0; r < ABC_BLKS; r++) {
                    a += g_part[r][0][j];
                    b += g_part[r][1][j];
                    c += g_part[r][2][j];
                }
                g_A[j] = a; g_Bv[j] = b; g_C[j] = c + agg_b[j];
            }
            if (threadIdx.x == 0) g_abc_ctr = 0;
        }
    } else if (blk < ABC_BLKS + 8) {
        const unsigned int* w32 = (const unsigned int*)mask;
        int flags = 0;
        int base = (blk - ABC_BLKS) * 2048 + threadIdx.x;
        #pragma unroll
        for (int t = 0; t < 8; t++) {
            unsigned int w = w32[base + t * 256];
            if (w == 0x3f800000u) flags |= 2;
            else if (w > 1u)      flags |= 1;
        }
        __shared__ int sfl;
        if (threadIdx.x == 0) sfl = 0;
        __syncthreads();
        if (flags) atomicOr(&sfl, flags);
        __syncthreads();
        if (threadIdx.x == 0 && sfl) atomicOr(&g_maskflags, sfl);
    } else {
        int i = (blk - ABC_BLKS - 8) * 256 + threadIdx.x;   // 0..2047
        if (i < NBV) g_cnt[i] = 0;
        ((float*)g_ctx)[i] = 0.f;
    }
}

// ---------------- K2: projection constants || vectorized token scatter || L2 prefetch ----------------
__global__ void k_mid(const float* __restrict__ var_emb,
                      const float* __restrict__ wq, const float* __restrict__ bq,
                      const float* __restrict__ wk, const float* __restrict__ bk,
                      const float* __restrict__ wv, const float* __restrict__ bvv,
                      const int* __restrict__ fid, const void* __restrict__ mask,
                      const float* __restrict__ values, const float* __restrict__ times,
                      const float* __restrict__ wo, const float* __restrict__ cw1) {
    int blk = blockIdx.x;
    if (blk < 201) {
        int p = blk / 67, row = blk % 67;
        const float* W  = (p == 0) ? wq : (p == 1 ? wk : wv);
        const float* bb = (p == 0) ? bq : (p == 1 ? bk : bvv);
        int j = threadIdx.x;
        if (row < Vc) {
            const float* ve = &var_emb[row * DVc];
            float s = 0.f;
            #pragma unroll
            for (int i = 0; i < DVc; i++) s += ve[i] * W[i * Dc + j];
            g_Pvar[p][row][j] = s;
        } else {
            const float* src = (row == Vc) ? g_A : (row == Vc + 1 ? g_Bv : g_C);
            float s = 0.f;
            #pragma unroll 8
            for (int i = 0; i < DAGG; i++) s += src[i] * W[(DVc + i) * Dc + j];
            if      (row == Vc)     g_pa[p][j] = s;
            else if (row == Vc + 1) g_pb[p][j] = s;
            else                    g_pc[p][j] = s + bb[j];
        }
    } else if (blk < 265) {
        // 4 tokens per thread, vectorized loads
        int t4 = (blk - 201) * 256 + threadIdx.x;   // token quad index
        int fl = g_maskflags;
        bool ok[4];
        if (fl & 2) {
            float4 m4 = ((const float4*)mask)[t4];
            ok[0] = m4.x != 0.f; ok[1] = m4.y != 0.f; ok[2] = m4.z != 0.f; ok[3] = m4.w != 0.f;
        } else if (fl & 1) {
            unsigned int u = ((const unsigned int*)mask)[t4];
            ok[0] = (u & 0xffu) != 0; ok[1] = (u & 0xff00u) != 0;
            ok[2] = (u & 0xff0000u) != 0; ok[3] = (u & 0xff000000u) != 0;
        } else {
            int4 m4 = ((const int4*)mask)[t4];
            ok[0] = m4.x != 0; ok[1] = m4.y != 0; ok[2] = m4.z != 0; ok[3] = m4.w != 0;
        }
        if (!(ok[0] | ok[1] | ok[2] | ok[3])) return;
        float4 vv = ((const float4*)values)[t4];
        float4 tt = ((const float4*)times)[t4];
        int4   ff = ((const int4*)fid)[t4];
        int b = (t4 * 4) >> 13;
        float va[4] = {vv.x, vv.y, vv.z, vv.w};
        float ta[4] = {tt.x, tt.y, tt.z, tt.w};
        int   fa[4] = {ff.x, ff.y, ff.z, ff.w};
        #pragma unroll
        for (int u = 0; u < 4; u++) {
            if (!ok[u]) continue;
            int bv = b * Vc + fa[u];
            int pos = atomicAdd(&g_cnt[bv], 1);
            g_tok[bv * CAP + pos] = make_float2(va[u], ta[u]);
        }
    } else {
        // ---- PF: warm L2 with wo and cw1 for k_f1/k_f2 ----
        int chunk = blk - 265;                  // 0..31
        const float4* s4 = (chunk < 16) ? (const float4*)wo : (const float4*)cw1;
        int base = (chunk & 15) * 1024 + threadIdx.x;   // 16KB chunks
        float acc = 0.f;
        #pragma unroll
        for (int i = 0; i < 4; i++) {
            float4 w = __ldcg(&s4[base + i * 256]);
            acc += w.x + w.y + w.z + w.w;
        }
        if (acc == 1.2345e-37f) g_sink = acc;   // DCE guard, never taken
    }
}

// ---------------- K3: segmented attention, affine-score form ----------------
__global__ void __launch_bounds__(256) k_attn(const int* __restrict__ fid,
                                              const float* __restrict__ values,
                                              const float* __restrict__ times) {
    int bv = blockIdx.x;
    int b = bv >> 6, v = bv & (Vc - 1);
    int tid = threadIdx.x;             // dim index d = h*32+lane
    int lane = tid & 31;
    int n = g_cnt[bv];

    float va = g_pa[2][tid], vb = g_pb[2][tid], vc = g_pc[2][tid];

    if (n == 0) {
        int t0 = b * Sc;
        float vx = g_Pvar[2][fid[t0]][tid] + values[t0] * va + times[t0] * vb + vc;
        atomicAdd(&g_ctx[b][tid], vx);
        return;
    }

    const float2* tok = &g_tok[bv * CAP];

    float s_v = 0.f, s_t = 0.f;
    for (int i = lane; i < n; i += 32) {
        float2 vt = tok[i];
        s_v += vt.x; s_t += vt.y;
    }
    #pragma unroll
    for (int o = 16; o > 0; o >>= 1) {
        s_v += __shfl_xor_sync(0xffffffffu, s_v, o);
        s_t += __shfl_xor_sync(0xffffffffu, s_t, o);
    }
    float inv_n = 1.0f / (float)n;
    float mv = s_v * inv_n, mt = s_t * inv_n;

    float q  = g_Pvar[0][v][tid] + mv * g_pa[0][tid] + mt * g_pb[0][tid] + g_pc[0][tid];
    float kk = g_Pvar[1][v][tid] + g_pc[1][tid];

    const float scale = 0.17677669529663687f;  // 1/sqrt(32)
    float al = q * kk, be = q * g_pa[1][tid], ga = q * g_pb[1][tid];
    #pragma unroll
    for (int o = 16; o > 0; o >>= 1) {
        al += __shfl_xor_sync(0xffffffffu, al, o);
        be += __shfl_xor_sync(0xffffffffu, be, o);
        ga += __shfl_xor_sync(0xffffffffu, ga, o);
    }
    al *= scale; be *= scale; ga *= scale;

    float m = -1e30f, l = 0.f, sv = 0.f, st = 0.f;
    for (int i = lane; i < n; i += 32) {
        float2 vt = tok[i];
        float s  = al + be * vt.x + ga * vt.y;
        float nm = fmaxf(m, s);
        float c  = __expf(m - nm);
        float e  = __expf(s - nm);
        l  = l * c + e;
        sv = sv * c + e * vt.x;
        st = st * c + e * vt.y;
        m = nm;
    }
    #pragma unroll
    for (int o = 16; o > 0; o >>= 1) {
        float m2  = __shfl_xor_sync(0xffffffffu, m, o);
        float l2  = __shfl_xor_sync(0xffffffffu, l, o);
        float sv2 = __shfl_xor_sync(0xffffffffu, sv, o);
        float st2 = __shfl_xor_sync(0xffffffffu, st, o);
        float nm = fmaxf(m, m2);
        float c1 = __expf(m - nm), c2 = __expf(m2 - nm);
        l  = l * c1 + l2 * c2;
        sv = sv * c1 + sv2 * c2;
        st = st * c1 + st2 * c2;
        m = nm;
    }
    float wv = sv / l, wt = st / l;
    float ctx = g_Pvar[2][v][tid] + vc + wv * va + wt * vb;
    atomicAdd(&g_ctx[b][tid], ctx);
}

// ---------------- K4a: GEMV1 in 32-col slices (64 blocks) ----------------
__global__ void __launch_bounds__(256) k_f1(const float* __restrict__ wo,
                                            const float* __restrict__ bo) {
    int b = blockIdx.x >> 3, slice = blockIdx.x & 7;
    int tid = threadIdx.x;
    int col = tid & 31, r = tid >> 5;       // 8 row-partitions x 32 cols
    int jg = slice * 32 + col;              // global output column
    __shared__ float sm[Dc];
    __shared__ float part[8][32];

    sm[tid] = g_ctx[b][tid] * (1.0f / Vc);
    __syncthreads();

    float acc = 0.f;
    #pragma unroll
    for (int ii = 0; ii < 32; ii++) {
        int i = r * 32 + ii;
        acc += sm[i] * wo[i * Dc + jg];
    }
    part[r][col] = acc;
    __syncthreads();
    if (r < 4) part[r][col] += part[r + 4][col];
    __syncthreads();
    if (r == 0)
        g_sf[b][jg] = part[0][col] + part[1][col] + part[2][col] + part[3][col] + bo[jg];
}

// ---------------- K4b: GEMV2 + relu + dot, slice partials, last-block finalize ----------------
__global__ void __launch_bounds__(256) k_f2(const float* __restrict__ cw1,
                                            const float* __restrict__ cb1,
                                            const float* __restrict__ cw2,
                                            const float* __restrict__ cb2,
                                            float* __restrict__ out) {
    int b = blockIdx.x >> 3, slice = blockIdx.x & 7;
    int tid = threadIdx.x;
    int col = tid & 31, r = tid >> 5;
    int jg = slice * 32 + col;
    __shared__ float sf[Dc];
    __shared__ float part[8][32];

    sf[tid] = g_sf[b][tid];
    __syncthreads();

    float acc = 0.f;
    #pragma unroll
    for (int ii = 0; ii < 32; ii++) {
        int i = r * 32 + ii;
        acc += sf[i] * cw1[i * Dc + jg];
    }
    part[r][col] = acc;
    __syncthreads();
    if (r < 4) part[r][col] += part[r + 4][col];
    __syncthreads();
    if (r == 0) {
        float h = part[0][col] + part[1][col] + part[2][col] + part[3][col] + cb1[jg];
        h = fmaxf(h, 0.f);
        float s = h * cw2[jg];
        #pragma unroll
        for (int o = 16; o > 0; o >>= 1) s += __shfl_xor_sync(0xffffffffu, s, o);
        if (col == 0) {
            g_p2[b][slice] = s;
            __threadfence();
            int done = atomicAdd(&g_ctr2[b], 1);
            if (done == 7) {
                float tot = 0.f;
                #pragma unroll
                for (int k = 0; k < 8; k++) tot += g_p2[b][k];
                out[b] = tot + cb2[0];
                g_ctr2[b] = 0;   // reset for next replay
            }
        }
    }
}

// ---------------- launch ----------------
extern "C" void kernel_launch(void* const* d_in, const int* in_sizes, int n_in,
                              void* d_out, int out_size) {
    const float* times   = (const float*)d_in[0];
    const int*   fid     = (const int*)  d_in[1];
    const float* values  = (const float*)d_in[2];
    const void*  mask    = (const void*) d_in[3];
    const float* me_w    = (const float*)d_in[4];
    const float* me_b    = (const float*)d_in[5];
    const float* var_emb = (const float*)d_in[6];
    const float* time_w  = (const float*)d_in[7];
    const float* time_b  = (const float*)d_in[8];
    const float* agg_w   = (const float*)d_in[9];
    const float* agg_b   = (const float*)d_in[10];
    const float* wq = (const float*)d_in[11]; const float* bq  = (const float*)d_in[12];
    const float* wk = (const float*)d_in[13]; const float* bk  = (const float*)d_in[14];
    const float* wv = (const float*)d_in[15]; const float* bvv = (const float*)d_in[16];
    const float* wo = (const float*)d_in[17]; const float* bo  = (const float*)d_in[18];
    const float* cw1 = (const float*)d_in[19]; const float* cb1 = (const float*)d_in[20];
    const float* cw2 = (const float*)d_in[21]; const float* cb2 = (const float*)d_in[22];
    float* out = (float*)d_out;

    k_init <<<ABC_BLKS + 8 + 8, 256>>>(me_w, me_b, time_w, time_b, agg_w, agg_b, mask);
    k_mid  <<<201 + 64 + PF_BLKS, 256>>>(var_emb, wq, bq, wk, bk, wv, bvv,
                                         fid, mask, values, times, wo, cw1);
    k_attn <<<NBV, 256>>>(fid, values, times);
    k_f1   <<<64, 256>>>(wo, bo);
    k_f2   <<<64, 256>>>(cw1, cb1, cw2, cb2, out);
}